// round 11
// baseline (speedup 1.0000x reference)
#include <cuda_runtime.h>
#include <cuda_fp16.h>
#include <stdint.h>

#define B_  128
#define G_  20000
#define P_  4096
#define KT  64
#define NT  32
#define NCTA   (P_/NT)       // 128
#define NCHUNK 313           // 312 full 64-k chunks + one 32-k tail
#define BN_EPS 1e-5f

// dynamic smem layout (all pitches 144B = 36 u32: conflict-free)
#define A_ROWB     144                  // 64 halves (128B) + 16B pad
#define A_STAGE_B  (128*A_ROWB)         // 18432; ring of 3
#define WF32_BASE  (3*A_STAGE_B)        // 55296
#define WF32_ROWB  144                  // 32 floats + 16B pad
#define WF32_ARR   (64*WF32_ROWB)       // 9216 per array
#define WF32_STAGE (3*WF32_ARR)         // Wk | mapp | Wa = 27648; ring of 3
#define WF16_BASE  (WF32_BASE + 3*WF32_STAGE)   // 138240
#define W_ARR_B    (32*144)             // fp16 [n][k]: 32 cols x 36 u32 = 4608
#define WF16_STAGE (2*W_ARR_B)          // W + T = 9216; ring of 2
#define SMEM_DYN   (WF16_BASE + 2*WF16_STAGE + 256)   // 156928 (~153 KB)
#define SHS 34                           // epilogue f32 row stride

__device__ __half g_Ah[B_ * G_];
__device__ float g_dpart[B_ * NCTA];

__device__ __forceinline__ uint32_t smem_u32(const void* p) {
    uint32_t a;
    asm("{ .reg .u64 t; cvta.to.shared.u64 t, %1; cvt.u32.u64 %0, t; }"
        : "=r"(a) : "l"(p));
    return a;
}
#define CPA16(dst, src) \
    asm volatile("cp.async.cg.shared.global [%0], [%1], 16;" :: "r"(dst), "l"(src))
#define CPA_COMMIT() asm volatile("cp.async.commit_group;")
#define CPA_WAIT1()  asm volatile("cp.async.wait_group 1;")

__device__ __forceinline__ void mma_f16(float* d, const uint32_t* a, uint32_t b0, uint32_t b1) {
    asm volatile(
        "mma.sync.aligned.m16n8k16.row.col.f32.f16.f16.f32 "
        "{%0,%1,%2,%3}, {%4,%5,%6,%7}, {%8,%9}, {%0,%1,%2,%3};"
        : "+f"(d[0]), "+f"(d[1]), "+f"(d[2]), "+f"(d[3])
        : "r"(a[0]), "r"(a[1]), "r"(a[2]), "r"(a[3]), "r"(b0), "r"(b1));
}

// ---------------- pre-convert A: fp32 -> fp16 global ----------------
__global__ __launch_bounds__(256) void presplit_kernel(const float* __restrict__ A) {
    int i4 = blockIdx.x * 256 + threadIdx.x;   // 640000 float4s exactly
    float4 v = ((const float4*)A)[i4];
    __half2 h0 = __floats2half2_rn(v.x, v.y);
    __half2 h1 = __floats2half2_rn(v.z, v.w);
    ((uint2*)g_Ah)[i4] = make_uint2(*(uint32_t*)&h0, *(uint32_t*)&h1);
}

// ---------------- fused main kernel ----------------
__global__ __launch_bounds__(256, 1) void bioxnet_fused_kernel(
    const float* __restrict__ mapp, const float* __restrict__ Wk,
    const float* __restrict__ Wa, const float* __restrict__ att_bias,
    const float* __restrict__ gamma, const float* __restrict__ beta,
    const float* __restrict__ dec_w,
    float* __restrict__ out_outcome, float* __restrict__ out_att)
{
    extern __shared__ __align__(16) char sp[];
    __shared__ float redS[8][NT], redQ[8][NT], s_mean[NT], s_rstd[NT];

    const int tid  = threadIdx.x;
    const int lane = tid & 31;
    const int wrp  = tid >> 5;
    const int gr   = lane >> 2;   // 0..7
    const int tc   = lane & 3;    // 0..3
    const int wr   = wrp >> 1;    // 0..3: 32-row group
    const int wc   = wrp & 1;     // 0..1: 16-col group
    const int col0 = blockIdx.x * NT;
    const uint32_t sb = smem_u32(sp);

    // A cp.async: row = tid>>1, 4 of 8 16B units (each unit = 8 halves)
    const int arow = tid >> 1;
    const int au0  = (tid & 1) * 4;
    const __half* gA = g_Ah + (long)arow * G_;
    const uint32_t adst = (uint32_t)(arow * A_ROWB + au0 * 16);

#define CPA_A(chunk, st) do {                                            \
        uint32_t _b = sb + (uint32_t)(st) * A_STAGE_B + adst;            \
        int _k0 = (chunk) * KT + au0 * 8;                                \
        _Pragma("unroll")                                                \
        for (int _u = 0; _u < 4; _u++)                                   \
            if (_k0 + _u * 8 < G_) CPA16(_b + _u * 16, gA + _k0 + _u * 8); \
    } while (0)

    // W cp.async: k-row = tid>>2, 2 of 8 16B units per array
    const int wkr0 = tid >> 2;              // 0..63
    const int wu0  = (tid & 3) * 2;         // 16B unit pair
    const long wgo = (long)wkr0 * P_ + col0 + wu0 * 4;
    const uint32_t wdst = (uint32_t)(wkr0 * WF32_ROWB + wu0 * 16);

#define CPA_W(chunk, st) do {                                              \
        if ((chunk) * KT + wkr0 < G_) {                                    \
            uint32_t _b = sb + WF32_BASE + (uint32_t)(st) * WF32_STAGE + wdst; \
            long _g = (long)(chunk) * KT * P_ + wgo;                       \
            CPA16(_b,              Wk   + _g); CPA16(_b + 16,              Wk   + _g + 4); \
            CPA16(_b +   WF32_ARR, mapp + _g); CPA16(_b + 16 +   WF32_ARR, mapp + _g + 4); \
            CPA16(_b + 2*WF32_ARR, Wa   + _g); CPA16(_b + 16 + 2*WF32_ARR, Wa   + _g + 4); \
        }                                                                  \
    } while (0)

    // CONV: thread -> col wn, 8 k rows starting kq*8 (4 packed u32 per array)
    const int wn = tid & 31;
    const int kq = tid >> 5;   // 0..7

#define CONV_W(st32, st16) do {                                                     \
        const float* _f = (const float*)(sp + WF32_BASE + (st32) * WF32_STAGE);     \
        uint32_t* _w = (uint32_t*)(sp + WF16_BASE + (st16) * WF16_STAGE);           \
        uint32_t* _t = _w + (W_ARR_B / 4);                                          \
        _Pragma("unroll")                                                           \
        for (int _j = 0; _j < 4; _j++) {                                            \
            const int _k = kq * 8 + _j * 2;                                         \
            float _a0 = _f[_k * 36 + wn],        _a1 = _f[(_k + 1) * 36 + wn];      \
            float _m0 = _f[2304 + _k * 36 + wn], _m1 = _f[2304 + (_k + 1) * 36 + wn];\
            float _b0 = _f[4608 + _k * 36 + wn], _b1 = _f[4608 + (_k + 1) * 36 + wn];\
            __half2 _pw = __floats2half2_rn(_a0 * _m0, _a1 * _m1);                  \
            __half2 _pt = __floats2half2_rn(_b0, _b1);                              \
            _w[wn * 36 + kq * 4 + _j] = *(uint32_t*)&_pw;                           \
            _t[wn * 36 + kq * 4 + _j] = *(uint32_t*)&_pt;                           \
        }                                                                           \
    } while (0)

    float accH[2][2][4], accT[2][2][4];
#pragma unroll
    for (int rt = 0; rt < 2; rt++)
#pragma unroll
        for (int nt = 0; nt < 2; nt++)
#pragma unroll
            for (int i = 0; i < 4; i++) { accH[rt][nt][i] = 0.f; accT[rt][nt][i] = 0.f; }

    // MMA over k16 steps [kh0, kh1) of chunk in A stage stA / fp16 stage st16
#define MMA_K(stA, st16, kh0, kh1) do {                                            \
        const uint32_t* aH = (const uint32_t*)(sp + (stA) * A_STAGE_B);            \
        const uint32_t* wW = (const uint32_t*)(sp + WF16_BASE + (st16) * WF16_STAGE); \
        const uint32_t* wT = wW + (W_ARR_B / 4);                                   \
        _Pragma("unroll")                                                          \
        for (int kh = (kh0); kh < (kh1); kh++) {                                   \
            uint32_t ah[2][4];                                                     \
            _Pragma("unroll")                                                      \
            for (int rt = 0; rt < 2; rt++) {                                       \
                const int o = (wr * 32 + rt * 16 + gr) * 36 + kh * 8 + tc;         \
                ah[rt][0] = aH[o];                                                 \
                ah[rt][1] = aH[o + 288];   /* +8 rows */                           \
                ah[rt][2] = aH[o + 4];     /* +8 k    */                           \
                ah[rt][3] = aH[o + 292];                                           \
            }                                                                      \
            _Pragma("unroll")                                                      \
            for (int nt = 0; nt < 2; nt++) {                                       \
                const int o = (wc * 16 + nt * 8 + gr) * 36 + kh * 8 + tc;          \
                uint32_t w0 = wW[o], w1 = wW[o + 4];                               \
                uint32_t t0 = wT[o], t1 = wT[o + 4];                               \
                _Pragma("unroll")                                                  \
                for (int rt = 0; rt < 2; rt++) {                                   \
                    mma_f16(accH[rt][nt], ah[rt], w0, w1);                         \
                    mma_f16(accT[rt][nt], ah[rt], t0, t1);                         \
                }                                                                  \
            }                                                                      \
        }                                                                          \
    } while (0)

    // -------- prologue: chunks 0,1 in flight --------
    CPA_A(0, 0); CPA_W(0, 0); CPA_COMMIT();
    CPA_A(1, 1); CPA_W(1, 1); CPA_COMMIT();

    int stC = 0;   // stage of chunk i      (i % 3)
    int stN = 2;   // stage of chunk i + 2  ((i+2) % 3)
#pragma unroll 1
    for (int i = 0; i < NCHUNK; i++) {
        CPA_WAIT1();       // chunk i landed (chunk i+1 pending)
        __syncthreads();   // visibility CTA-wide; all warps past MMA(i-1)

        if (i + 2 < NCHUNK) { CPA_A(i + 2, stN); CPA_W(i + 2, stN); }
        CPA_COMMIT();      // unconditional: uniform group count

        CONV_W(stC, i & 1);
        __syncthreads();   // fp16 W/T visible before MMA

        MMA_K(stC, i & 1, 0, 2);
        if (i != NCHUNK - 1) MMA_K(stC, i & 1, 2, 4);   // tail chunk has only 32 k

        stC = (stC == 2) ? 0 : stC + 1;
        stN = (stN == 2) ? 0 : stN + 1;
    }
    __syncthreads();

    // ---- spill accumulators (GEMM bias omitted: cancels in BN mean-subtract) ----
    float* sH = (float*)sp;
    float* sT = (float*)(sp + 17408);
#pragma unroll
    for (int rt = 0; rt < 2; rt++) {
#pragma unroll
        for (int nt = 0; nt < 2; nt++) {
            const int row0 = wr * 32 + rt * 16 + gr;
            const int col  = wc * 16 + nt * 8 + 2 * tc;
            *(float2*)&sH[(row0    ) * SHS + col] = make_float2(accH[rt][nt][0], accH[rt][nt][1]);
            *(float2*)&sH[(row0 + 8) * SHS + col] = make_float2(accH[rt][nt][2], accH[rt][nt][3]);
            *(float2*)&sT[(row0    ) * SHS + col] = make_float2(accT[rt][nt][0], accT[rt][nt][1]);
            *(float2*)&sT[(row0 + 8) * SHS + col] = make_float2(accT[rt][nt][2], accT[rt][nt][3]);
        }
    }
    __syncthreads();

    // ---- batchnorm stats over all 128 rows (CTA-local) ----
    const int col = tid & 31;
    const int seg = tid >> 5;
    {
        float s = 0.f, q = 0.f;
#pragma unroll
        for (int r = 0; r < 16; r++) {
            float h = sH[(seg * 16 + r) * SHS + col];
            s += h; q += h * h;
        }
        redS[seg][col] = s;
        redQ[seg][col] = q;
    }
    __syncthreads();
    if (tid < 32) {
        float ss = 0.f, qq = 0.f;
#pragma unroll
        for (int i = 0; i < 8; i++) { ss += redS[i][tid]; qq += redQ[i][tid]; }
        float mean = ss * (1.0f / B_);
        float var  = qq * (1.0f / B_) - mean * mean;
        s_mean[tid] = mean;
        s_rstd[tid] = rsqrtf(var + BN_EPS);
    }
    __syncthreads();

    // ---- BN + tanh + sigmoid gate, outputs, decision partials ----
    const float mean = s_mean[col], rstd = s_rstd[col];
    const float gm = gamma[col0 + col], bt = beta[col0 + col];
    const float ab = att_bias[col0 + col], dw = dec_w[col0 + col];
#pragma unroll 4
    for (int r = 0; r < 16; r++) {
        int row = seg * 16 + r;
        float h  = sH[row * SHS + col];
        float hn = (h - mean) * rstd * gm + bt;
        float th = tanhf(hn);
        float z  = sT[row * SHS + col] + ab;
        float sg = 1.0f / (1.0f + __expf(-z));
        float o  = th * sg;
        long ofs = (long)row * P_ + col0 + col;
        out_outcome[ofs] = o;
        out_att[ofs]     = sg;
        float p = o * dw;
#pragma unroll
        for (int off = 16; off > 0; off >>= 1)
            p += __shfl_xor_sync(0xffffffffu, p, off);
        if (col == 0) g_dpart[row * NCTA + blockIdx.x] = p;
    }
}

__global__ __launch_bounds__(512) void bioxnet_decision_kernel(
    const float* __restrict__ dec_b, float* __restrict__ out_dec)
{
    __shared__ float red[4][B_];
    int t = threadIdx.x;
    int row = t >> 2;
    int seg = t & 3;
    const float4* p = (const float4*)(g_dpart + row * NCTA + seg * 32);
    float s = 0.f;
#pragma unroll
    for (int i = 0; i < 8; i++) {
        float4 v = p[i];
        s += v.x + v.y + v.z + v.w;
    }
    red[seg][row] = s;
    __syncthreads();
    if (t < B_) out_dec[t] = dec_b[0] + red[0][t] + red[1][t] + red[2][t] + red[3][t];
}

extern "C" void kernel_launch(void* const* d_in, const int* in_sizes, int n_in,
                              void* d_out, int out_size)
{
    (void)in_sizes; (void)n_in; (void)out_size;
    const float* A        = (const float*)d_in[0];
    const float* mapp     = (const float*)d_in[1];
    const float* Wk       = (const float*)d_in[2];
    // d_in[3] = bias: cancels exactly in batchnorm mean subtraction
    const float* Wa       = (const float*)d_in[4];
    const float* att_bias = (const float*)d_in[5];
    const float* gamma    = (const float*)d_in[6];
    const float* beta     = (const float*)d_in[7];
    const float* dec_w    = (const float*)d_in[8];
    const float* dec_b    = (const float*)d_in[9];

    float* out = (float*)d_out;
    float* out_outcome = out;
    float* out_dec     = out + (long)B_ * P_;
    float* out_att     = out + (long)B_ * P_ + B_;

    cudaFuncSetAttribute(bioxnet_fused_kernel,
                         cudaFuncAttributeMaxDynamicSharedMemorySize, SMEM_DYN);

    presplit_kernel<<<2500, 256>>>(A);
    bioxnet_fused_kernel<<<NCTA, 256, SMEM_DYN>>>(mapp, Wk, Wa, att_bias,
                                                  gamma, beta, dec_w,
                                                  out_outcome, out_att);
    bioxnet_decision_kernel<<<1, 512>>>(dec_b, out_dec);
}

// round 12
// speedup vs baseline: 1.3449x; 1.3449x over previous
#include <cuda_runtime.h>
#include <cuda_fp16.h>
#include <stdint.h>

#define B_  128
#define G_  20000
#define P_  4096
#define KT  32
#define NT  32
#define NCTA   (P_/NT)     // 128
#define NCHUNK (G_/KT)     // 625 exact
#define BN_EPS 1e-5f

// dynamic smem byte offsets
#define A_ROWB     80                  // 32 halves + 16B pad -> u32 stride 20, conflict-free
#define A_STAGE_B  (128*A_ROWB)        // 10240; ring of 8
#define WF32_BASE  (8*A_STAGE_B)       // 81920
#define WF32_STAGE 12288               // Wk 4KB | mapp 4KB | Wa 4KB; ring of 4
#define WF16_BASE  (WF32_BASE + 4*WF32_STAGE)   // 131072
#define W_ARR_B    2560                // fp16 [n][k] stride-20 array
#define WF16_STAGE (2*W_ARR_B)         // W + T; ring of 2
#define SMEM_DYN   (WF16_BASE + 2*WF16_STAGE + 256)   // ~138.5 KB
#define SHS 34                          // epilogue f32 row stride

__device__ __half g_Ah[B_ * G_];
__device__ float g_dpart[B_ * NCTA];

__device__ __forceinline__ uint32_t smem_u32(const void* p) {
    uint32_t a;
    asm("{ .reg .u64 t; cvta.to.shared.u64 t, %1; cvt.u32.u64 %0, t; }"
        : "=r"(a) : "l"(p));
    return a;
}
#define CPA16(dst, src) \
    asm volatile("cp.async.cg.shared.global [%0], [%1], 16;" :: "r"(dst), "l"(src))
#define CPA_COMMIT() asm volatile("cp.async.commit_group;")
#define CPA_WAIT3()  asm volatile("cp.async.wait_group 3;")

__device__ __forceinline__ void mma_f16(float* d, const uint32_t* a, uint32_t b0, uint32_t b1) {
    asm volatile(
        "mma.sync.aligned.m16n8k16.row.col.f32.f16.f16.f32 "
        "{%0,%1,%2,%3}, {%4,%5,%6,%7}, {%8,%9}, {%0,%1,%2,%3};"
        : "+f"(d[0]), "+f"(d[1]), "+f"(d[2]), "+f"(d[3])
        : "r"(a[0]), "r"(a[1]), "r"(a[2]), "r"(a[3]), "r"(b0), "r"(b1));
}

// ---------------- pre-convert A: fp32 -> fp16 global ----------------
__global__ __launch_bounds__(256) void presplit_kernel(const float* __restrict__ A) {
    int i4 = blockIdx.x * 256 + threadIdx.x;   // 640000 float4s exactly
    float4 v = ((const float4*)A)[i4];
    __half2 h0 = __floats2half2_rn(v.x, v.y);
    __half2 h1 = __floats2half2_rn(v.z, v.w);
    ((uint2*)g_Ah)[i4] = make_uint2(*(uint32_t*)&h0, *(uint32_t*)&h1);
}

// ---------------- fused main kernel ----------------
__global__ __launch_bounds__(256, 1) void bioxnet_fused_kernel(
    const float* __restrict__ mapp, const float* __restrict__ Wk,
    const float* __restrict__ Wa, const float* __restrict__ att_bias,
    const float* __restrict__ gamma, const float* __restrict__ beta,
    const float* __restrict__ dec_w,
    float* __restrict__ out_outcome, float* __restrict__ out_att)
{
    extern __shared__ __align__(16) char sp[];
    __shared__ float redS[8][NT], redQ[8][NT], s_mean[NT], s_rstd[NT];

    const int tid  = threadIdx.x;
    const int lane = tid & 31;
    const int wrp  = tid >> 5;
    const int gr   = lane >> 2;   // 0..7
    const int tc   = lane & 3;    // 0..3
    const int wr   = wrp >> 1;    // 0..3: 32-row group
    const int wc   = wrp & 1;     // 0..1: 16-col group
    const int col0 = blockIdx.x * NT;
    const uint32_t sb = smem_u32(sp);

    // A cp.async: thread -> (row = tid>>1, 2 of 4 16B units)
    const int arow = tid >> 1;
    const int auh  = (tid & 1) * 2;
    const __half* gH = g_Ah + (long)arow * G_ + auh * 8;
    const uint32_t ad0 = (uint32_t)(arow * A_ROWB + auh * 16);

#define CPA_A(chunk, st) do {                                 \
        uint32_t _b = sb + (uint32_t)(st) * A_STAGE_B + ad0;  \
        const __half* _h = gH + (chunk) * KT;                 \
        CPA16(_b, _h);  CPA16(_b + 16, _h + 8);               \
    } while (0)

    // W cp.async: thread -> row wkr0 = tid>>3, 16B unit wc0 = tid&7, one per array
    const int wkr0 = tid >> 3;
    const int wc0  = tid & 7;
    const long wgo = (long)wkr0 * P_ + col0 + wc0 * 4;
    const uint32_t wd0 = (uint32_t)(wkr0 * 128 + wc0 * 16);

#define CPA_W(chunk, st) do {                                             \
        uint32_t _b = sb + WF32_BASE + (uint32_t)(st) * WF32_STAGE + wd0; \
        long _g = (long)(chunk) * KT * P_ + wgo;                          \
        CPA16(_b,         Wk   + _g);                                     \
        CPA16(_b + 4096,  mapp + _g);                                     \
        CPA16(_b + 8192,  Wa   + _g);                                     \
    } while (0)

    // CONV: thread -> col wn, 4 k rows starting wkq*4 (reads staged fp32)
    const int wn  = tid & 31;
    const int wkq = tid >> 5;   // 0..7

#define CONV_W(st32, st16) do {                                                   \
        const float* _f = (const float*)(sp + WF32_BASE + (st32) * WF32_STAGE);   \
        uint32_t* _w = (uint32_t*)(sp + WF16_BASE + (st16) * WF16_STAGE);         \
        uint32_t* _t = _w + (W_ARR_B / 4);                                        \
        const int _k0 = wkq * 4;                                                  \
        float _a0 = _f[(_k0    ) * 32 + wn], _m0 = _f[1024 + (_k0    ) * 32 + wn];\
        float _a1 = _f[(_k0 + 1) * 32 + wn], _m1 = _f[1024 + (_k0 + 1) * 32 + wn];\
        float _a2 = _f[(_k0 + 2) * 32 + wn], _m2 = _f[1024 + (_k0 + 2) * 32 + wn];\
        float _a3 = _f[(_k0 + 3) * 32 + wn], _m3 = _f[1024 + (_k0 + 3) * 32 + wn];\
        int _o = wn * 20 + wkq * 2;                                               \
        __half2 _p0 = __floats2half2_rn(_a0 * _m0, _a1 * _m1);                    \
        __half2 _p1 = __floats2half2_rn(_a2 * _m2, _a3 * _m3);                    \
        _w[_o] = *(uint32_t*)&_p0; _w[_o + 1] = *(uint32_t*)&_p1;                 \
        _a0 = _f[2048 + (_k0    ) * 32 + wn];                                     \
        _a1 = _f[2048 + (_k0 + 1) * 32 + wn];                                     \
        _a2 = _f[2048 + (_k0 + 2) * 32 + wn];                                     \
        _a3 = _f[2048 + (_k0 + 3) * 32 + wn];                                     \
        _p0 = __floats2half2_rn(_a0, _a1);                                        \
        _p1 = __floats2half2_rn(_a2, _a3);                                        \
        _t[_o] = *(uint32_t*)&_p0; _t[_o + 1] = *(uint32_t*)&_p1;                 \
    } while (0)

    float accH[2][2][4], accT[2][2][4];
#pragma unroll
    for (int rt = 0; rt < 2; rt++)
#pragma unroll
        for (int nt = 0; nt < 2; nt++)
#pragma unroll
            for (int i = 0; i < 4; i++) { accH[rt][nt][i] = 0.f; accT[rt][nt][i] = 0.f; }

    // MMA body for chunk j: A stage j&7, fp16 stage j&1
#define MMA_CHUNK(j) do {                                                          \
        const uint32_t* aH = (const uint32_t*)(sp + ((j) & 7) * A_STAGE_B);        \
        const uint32_t* wW = (const uint32_t*)(sp + WF16_BASE + ((j) & 1) * WF16_STAGE); \
        const uint32_t* wT = wW + (W_ARR_B / 4);                                   \
        _Pragma("unroll")                                                          \
        for (int kh = 0; kh < 2; kh++) {                                           \
            uint32_t ah[2][4];                                                     \
            _Pragma("unroll")                                                      \
            for (int rt = 0; rt < 2; rt++) {                                       \
                const int o = (wr * 32 + rt * 16 + gr) * 20 + kh * 8 + tc;         \
                ah[rt][0] = aH[o];                                                 \
                ah[rt][1] = aH[o + 160];                                           \
                ah[rt][2] = aH[o + 4];                                             \
                ah[rt][3] = aH[o + 164];                                           \
            }                                                                      \
            _Pragma("unroll")                                                      \
            for (int nt = 0; nt < 2; nt++) {                                       \
                const int o = (wc * 16 + nt * 8 + gr) * 20 + kh * 8 + tc;          \
                uint32_t w0 = wW[o], w1 = wW[o + 4];                               \
                uint32_t t0 = wT[o], t1 = wT[o + 4];                               \
                _Pragma("unroll")                                                  \
                for (int rt = 0; rt < 2; rt++) {                                   \
                    mma_f16(accH[rt][nt], ah[rt], w0, w1);                         \
                    mma_f16(accT[rt][nt], ah[rt], t0, t1);                         \
                }                                                                  \
            }                                                                      \
        }                                                                          \
    } while (0)

    // -------- prologue: chunks 0..2 in flight --------
    CPA_A(0, 0); CPA_W(0, 0); CPA_COMMIT();
    CPA_A(1, 1); CPA_W(1, 1); CPA_COMMIT();
    CPA_A(2, 2); CPA_W(2, 2); CPA_COMMIT();

#pragma unroll 1
    for (int i = 0; i < NCHUNK; i++) {
        __syncthreads();   // CONV(i-1) + MMA(i-2) complete CTA-wide; chunk i data coherent

        // prefetch chunk i+3: A stage (i+3)&7 (last read by MMA(i-5)),
        // W32 stage (i+3)&3 (last read by CONV(i-1), done pre-barrier)
        if (i + 3 < NCHUNK) { CPA_A(i + 3, (i + 3) & 7); CPA_W(i + 3, (i + 3) & 3); }
        CPA_COMMIT();      // unconditional: uniform group count

        if (i > 0) MMA_CHUNK(i - 1);   // overlaps in-flight cp.async

        CPA_WAIT3();       // pending <= {i+1, i+2, i+3} -> group i landed
        CONV_W(i & 3, i & 1);
    }
    __syncthreads();
    MMA_CHUNK(NCHUNK - 1);
    __syncthreads();

    // ---- spill accumulators (GEMM bias omitted: cancels in BN mean-subtract) ----
    float* sH = (float*)sp;
    float* sT = (float*)(sp + 17408);
#pragma unroll
    for (int rt = 0; rt < 2; rt++) {
#pragma unroll
        for (int nt = 0; nt < 2; nt++) {
            const int row0 = wr * 32 + rt * 16 + gr;
            const int col  = wc * 16 + nt * 8 + 2 * tc;
            *(float2*)&sH[(row0    ) * SHS + col] = make_float2(accH[rt][nt][0], accH[rt][nt][1]);
            *(float2*)&sH[(row0 + 8) * SHS + col] = make_float2(accH[rt][nt][2], accH[rt][nt][3]);
            *(float2*)&sT[(row0    ) * SHS + col] = make_float2(accT[rt][nt][0], accT[rt][nt][1]);
            *(float2*)&sT[(row0 + 8) * SHS + col] = make_float2(accT[rt][nt][2], accT[rt][nt][3]);
        }
    }
    __syncthreads();

    // ---- batchnorm stats over all 128 rows (CTA-local) ----
    const int col = tid & 31;
    const int seg = tid >> 5;
    {
        float s = 0.f, q = 0.f;
#pragma unroll
        for (int r = 0; r < 16; r++) {
            float h = sH[(seg * 16 + r) * SHS + col];
            s += h; q += h * h;
        }
        redS[seg][col] = s;
        redQ[seg][col] = q;
    }
    __syncthreads();
    if (tid < 32) {
        float ss = 0.f, qq = 0.f;
#pragma unroll
        for (int i = 0; i < 8; i++) { ss += redS[i][tid]; qq += redQ[i][tid]; }
        float mean = ss * (1.0f / B_);
        float var  = qq * (1.0f / B_) - mean * mean;
        s_mean[tid] = mean;
        s_rstd[tid] = rsqrtf(var + BN_EPS);
    }
    __syncthreads();

    // ---- BN + tanh + sigmoid gate, outputs, decision partials ----
    const float mean = s_mean[col], rstd = s_rstd[col];
    const float gm = gamma[col0 + col], bt = beta[col0 + col];
    const float ab = att_bias[col0 + col], dw = dec_w[col0 + col];
#pragma unroll 4
    for (int r = 0; r < 16; r++) {
        int row = seg * 16 + r;
        float h  = sH[row * SHS + col];
        float hn = (h - mean) * rstd * gm + bt;
        float th = tanhf(hn);
        float z  = sT[row * SHS + col] + ab;
        float sg = 1.0f / (1.0f + __expf(-z));
        float o  = th * sg;
        long ofs = (long)row * P_ + col0 + col;
        out_outcome[ofs] = o;
        out_att[ofs]     = sg;
        float p = o * dw;
#pragma unroll
        for (int off = 16; off > 0; off >>= 1)
            p += __shfl_xor_sync(0xffffffffu, p, off);
        if (col == 0) g_dpart[row * NCTA + blockIdx.x] = p;
    }
}

__global__ __launch_bounds__(512) void bioxnet_decision_kernel(
    const float* __restrict__ dec_b, float* __restrict__ out_dec)
{
    __shared__ float red[4][B_];
    int t = threadIdx.x;
    int row = t >> 2;
    int seg = t & 3;
    const float4* p = (const float4*)(g_dpart + row * NCTA + seg * 32);
    float s = 0.f;
#pragma unroll
    for (int i = 0; i < 8; i++) {
        float4 v = p[i];
        s += v.x + v.y + v.z + v.w;
    }
    red[seg][row] = s;
    __syncthreads();
    if (t < B_) out_dec[t] = dec_b[0] + red[0][t] + red[1][t] + red[2][t] + red[3][t];
}

extern "C" void kernel_launch(void* const* d_in, const int* in_sizes, int n_in,
                              void* d_out, int out_size)
{
    (void)in_sizes; (void)n_in; (void)out_size;
    const float* A        = (const float*)d_in[0];
    const float* mapp     = (const float*)d_in[1];
    const float* Wk       = (const float*)d_in[2];
    // d_in[3] = bias: cancels exactly in batchnorm mean subtraction
    const float* Wa       = (const float*)d_in[4];
    const float* att_bias = (const float*)d_in[5];
    const float* gamma    = (const float*)d_in[6];
    const float* beta     = (const float*)d_in[7];
    const float* dec_w    = (const float*)d_in[8];
    const float* dec_b    = (const float*)d_in[9];

    float* out = (float*)d_out;
    float* out_outcome = out;
    float* out_dec     = out + (long)B_ * P_;
    float* out_att     = out + (long)B_ * P_ + B_;

    cudaFuncSetAttribute(bioxnet_fused_kernel,
                         cudaFuncAttributeMaxDynamicSharedMemorySize, SMEM_DYN);

    presplit_kernel<<<2500, 256>>>(A);
    bioxnet_fused_kernel<<<NCTA, 256, SMEM_DYN>>>(mapp, Wk, Wa, att_bias,
                                                  gamma, beta, dec_w,
                                                  out_outcome, out_att);
    bioxnet_decision_kernel<<<1, 512>>>(dec_b, out_dec);
}

// round 13
// speedup vs baseline: 1.3469x; 1.0015x over previous
#include <cuda_runtime.h>
#include <cuda_fp16.h>
#include <stdint.h>

#define B_  128
#define G_  20000
#define P_  4096
#define KT  32
#define NT  32
#define NCTA   (P_/NT)     // 128
#define NCHUNK (G_/KT)     // 625 exact
#define BN_EPS 1e-5f

// dynamic smem byte offsets
#define A_ROWB     80                  // 32 halves + 16B pad -> u32 stride 20, conflict-free
#define A_STAGE_B  (128*A_ROWB)        // 10240; ring of 8
#define WF32_BASE  (8*A_STAGE_B)       // 81920
#define WF32_STAGE 12288               // Wk 4KB | mapp 4KB | Wa 4KB; ring of 4
#define WF16_BASE  (WF32_BASE + 4*WF32_STAGE)   // 131072
#define W_ARR_B    2560                // fp16 [n][k] stride-20 array
#define WF16_STAGE (2*W_ARR_B)         // W + T; ring of 2
#define SMEM_DYN   (WF16_BASE + 2*WF16_STAGE + 256)   // ~138.5 KB
#define SHS 34                          // epilogue f32 row stride

__device__ __half g_Ah[B_ * G_];
__device__ float g_dpart[B_ * NCTA];

__device__ __forceinline__ uint32_t smem_u32(const void* p) {
    uint32_t a;
    asm("{ .reg .u64 t; cvta.to.shared.u64 t, %1; cvt.u32.u64 %0, t; }"
        : "=r"(a) : "l"(p));
    return a;
}
#define CPA16(dst, src) \
    asm volatile("cp.async.cg.shared.global [%0], [%1], 16;" :: "r"(dst), "l"(src))
#define CPA_COMMIT() asm volatile("cp.async.commit_group;")
#define CPA_WAIT3()  asm volatile("cp.async.wait_group 3;")

__device__ __forceinline__ void mma_f16(float* d, const uint32_t* a, uint32_t b0, uint32_t b1) {
    asm volatile(
        "mma.sync.aligned.m16n8k16.row.col.f32.f16.f16.f32 "
        "{%0,%1,%2,%3}, {%4,%5,%6,%7}, {%8,%9}, {%0,%1,%2,%3};"
        : "+f"(d[0]), "+f"(d[1]), "+f"(d[2]), "+f"(d[3])
        : "r"(a[0]), "r"(a[1]), "r"(a[2]), "r"(a[3]), "r"(b0), "r"(b1));
}

// ---------------- pre-convert A: fp32 -> fp16 global ----------------
__global__ __launch_bounds__(256) void presplit_kernel(const float* __restrict__ A) {
    int i4 = blockIdx.x * 256 + threadIdx.x;   // 640000 float4s exactly
    float4 v = ((const float4*)A)[i4];
    __half2 h0 = __floats2half2_rn(v.x, v.y);
    __half2 h1 = __floats2half2_rn(v.z, v.w);
    ((uint2*)g_Ah)[i4] = make_uint2(*(uint32_t*)&h0, *(uint32_t*)&h1);
}

// ---------------- fused main kernel ----------------
__global__ __launch_bounds__(256, 1) void bioxnet_fused_kernel(
    const float* __restrict__ mapp, const float* __restrict__ Wk,
    const float* __restrict__ Wa, const float* __restrict__ att_bias,
    const float* __restrict__ gamma, const float* __restrict__ beta,
    const float* __restrict__ dec_w,
    float* __restrict__ out_outcome, float* __restrict__ out_att)
{
    extern __shared__ __align__(16) char sp[];
    __shared__ float redS[8][NT], redQ[8][NT], s_mean[NT], s_rstd[NT];

    const int tid  = threadIdx.x;
    const int lane = tid & 31;
    const int wrp  = tid >> 5;
    const int gr   = lane >> 2;   // 0..7
    const int tc   = lane & 3;    // 0..3
    const int wr   = wrp >> 1;    // 0..3: 32-row group
    const int wc   = wrp & 1;     // 0..1: 16-col group
    const int col0 = blockIdx.x * NT;
    const uint32_t sb = smem_u32(sp);

    // A cp.async: thread -> (row = tid>>1, 2 of 4 16B units)
    const int arow = tid >> 1;
    const int auh  = (tid & 1) * 2;
    const __half* gH = g_Ah + (long)arow * G_ + auh * 8;
    const uint32_t ad0 = (uint32_t)(arow * A_ROWB + auh * 16);

#define CPA_A(chunk, st) do {                                 \
        uint32_t _b = sb + (uint32_t)(st) * A_STAGE_B + ad0;  \
        const __half* _h = gH + (chunk) * KT;                 \
        CPA16(_b, _h);  CPA16(_b + 16, _h + 8);               \
    } while (0)

    // W cp.async: thread -> row wkr0 = tid>>3, 16B unit wc0 = tid&7, one per array
    const int wkr0 = tid >> 3;
    const int wc0  = tid & 7;
    const long wgo = (long)wkr0 * P_ + col0 + wc0 * 4;
    const uint32_t wd0 = (uint32_t)(wkr0 * 128 + wc0 * 16);

#define CPA_W(chunk, st) do {                                             \
        uint32_t _b = sb + WF32_BASE + (uint32_t)(st) * WF32_STAGE + wd0; \
        long _g = (long)(chunk) * KT * P_ + wgo;                          \
        CPA16(_b,         Wk   + _g);                                     \
        CPA16(_b + 4096,  mapp + _g);                                     \
        CPA16(_b + 8192,  Wa   + _g);                                     \
    } while (0)

    // CONV half jh (k-pairs jh*2..jh*2+1): thread -> col wn, rows wkq*4+..
    const int wn  = tid & 31;
    const int wkq = tid >> 5;   // 0..7

#define CONV_WH(st32, st16, jh) do {                                              \
        const float* _f = (const float*)(sp + WF32_BASE + (st32) * WF32_STAGE);   \
        uint32_t* _w = (uint32_t*)(sp + WF16_BASE + (st16) * WF16_STAGE);         \
        uint32_t* _t = _w + (W_ARR_B / 4);                                        \
        const int _k0 = wkq * 4 + (jh) * 2;                                       \
        float _a0 = _f[(_k0    ) * 32 + wn], _m0 = _f[1024 + (_k0    ) * 32 + wn];\
        float _a1 = _f[(_k0 + 1) * 32 + wn], _m1 = _f[1024 + (_k0 + 1) * 32 + wn];\
        float _b0 = _f[2048 + (_k0    ) * 32 + wn];                               \
        float _b1 = _f[2048 + (_k0 + 1) * 32 + wn];                               \
        __half2 _pw = __floats2half2_rn(_a0 * _m0, _a1 * _m1);                    \
        __half2 _pt = __floats2half2_rn(_b0, _b1);                                \
        _w[wn * 20 + wkq * 2 + (jh)] = *(uint32_t*)&_pw;                          \
        _t[wn * 20 + wkq * 2 + (jh)] = *(uint32_t*)&_pt;                          \
    } while (0)

    float accH[2][2][4], accT[2][2][4];
#pragma unroll
    for (int rt = 0; rt < 2; rt++)
#pragma unroll
        for (int nt = 0; nt < 2; nt++)
#pragma unroll
            for (int i = 0; i < 4; i++) { accH[rt][nt][i] = 0.f; accT[rt][nt][i] = 0.f; }

    // MMA half kh of chunk j: A stage j&7, fp16 stage j&1
#define MMA_KH(j, kh) do {                                                         \
        const uint32_t* aH = (const uint32_t*)(sp + ((j) & 7) * A_STAGE_B);        \
        const uint32_t* wW = (const uint32_t*)(sp + WF16_BASE + ((j) & 1) * WF16_STAGE); \
        const uint32_t* wT = wW + (W_ARR_B / 4);                                   \
        uint32_t ah[2][4];                                                         \
        _Pragma("unroll")                                                          \
        for (int rt = 0; rt < 2; rt++) {                                           \
            const int o = (wr * 32 + rt * 16 + gr) * 20 + (kh) * 8 + tc;           \
            ah[rt][0] = aH[o];                                                     \
            ah[rt][1] = aH[o + 160];                                               \
            ah[rt][2] = aH[o + 4];                                                 \
            ah[rt][3] = aH[o + 164];                                               \
        }                                                                          \
        _Pragma("unroll")                                                          \
        for (int nt = 0; nt < 2; nt++) {                                           \
            const int o = (wc * 16 + nt * 8 + gr) * 20 + (kh) * 8 + tc;            \
            uint32_t w0 = wW[o], w1 = wW[o + 4];                                   \
            uint32_t t0 = wT[o], t1 = wT[o + 4];                                   \
            _Pragma("unroll")                                                      \
            for (int rt = 0; rt < 2; rt++) {                                       \
                mma_f16(accH[rt][nt], ah[rt], w0, w1);                             \
                mma_f16(accT[rt][nt], ah[rt], t0, t1);                             \
            }                                                                      \
        }                                                                          \
    } while (0)

    // -------- prologue: chunks 0..2 in flight --------
    CPA_A(0, 0); CPA_W(0, 0); CPA_COMMIT();
    CPA_A(1, 1); CPA_W(1, 1); CPA_COMMIT();
    CPA_A(2, 2); CPA_W(2, 2); CPA_COMMIT();

#pragma unroll 1
    for (int i = 0; i < NCHUNK; i++) {
        __syncthreads();   // CONV(i-1) + MMA(i-2) complete CTA-wide

        // prefetch chunk i+3: A stage (i+3)&7, W32 stage (i+3)&3
        if (i + 3 < NCHUNK) { CPA_A(i + 3, (i + 3) & 7); CPA_W(i + 3, (i + 3) & 3); }
        CPA_COMMIT();      // unconditional: uniform group count
        CPA_WAIT3();       // pending <= {i+1, i+2, i+3} -> chunk i landed

        // interleave: conv ALU fills issue slots while tensor pipe drains HMMAs
        if (i > 0) MMA_KH(i - 1, 0);
        CONV_WH(i & 3, i & 1, 0);
        if (i > 0) MMA_KH(i - 1, 1);
        CONV_WH(i & 3, i & 1, 1);
    }
    __syncthreads();
    MMA_KH(NCHUNK - 1, 0);
    MMA_KH(NCHUNK - 1, 1);
    __syncthreads();

    // ---- spill accumulators (GEMM bias omitted: cancels in BN mean-subtract) ----
    float* sH = (float*)sp;
    float* sT = (float*)(sp + 17408);
#pragma unroll
    for (int rt = 0; rt < 2; rt++) {
#pragma unroll
        for (int nt = 0; nt < 2; nt++) {
            const int row0 = wr * 32 + rt * 16 + gr;
            const int col  = wc * 16 + nt * 8 + 2 * tc;
            *(float2*)&sH[(row0    ) * SHS + col] = make_float2(accH[rt][nt][0], accH[rt][nt][1]);
            *(float2*)&sH[(row0 + 8) * SHS + col] = make_float2(accH[rt][nt][2], accH[rt][nt][3]);
            *(float2*)&sT[(row0    ) * SHS + col] = make_float2(accT[rt][nt][0], accT[rt][nt][1]);
            *(float2*)&sT[(row0 + 8) * SHS + col] = make_float2(accT[rt][nt][2], accT[rt][nt][3]);
        }
    }
    __syncthreads();

    // ---- batchnorm stats over all 128 rows (CTA-local) ----
    const int col = tid & 31;
    const int seg = tid >> 5;
    {
        float s = 0.f, q = 0.f;
#pragma unroll
        for (int r = 0; r < 16; r++) {
            float h = sH[(seg * 16 + r) * SHS + col];
            s += h; q += h * h;
        }
        redS[seg][col] = s;
        redQ[seg][col] = q;
    }
    __syncthreads();
    if (tid < 32) {
        float ss = 0.f, qq = 0.f;
#pragma unroll
        for (int i = 0; i < 8; i++) { ss += redS[i][tid]; qq += redQ[i][tid]; }
        float mean = ss * (1.0f / B_);
        float var  = qq * (1.0f / B_) - mean * mean;
        s_mean[tid] = mean;
        s_rstd[tid] = rsqrtf(var + BN_EPS);
    }
    __syncthreads();

    // ---- BN + tanh + sigmoid gate, outputs, decision partials ----
    const float mean = s_mean[col], rstd = s_rstd[col];
    const float gm = gamma[col0 + col], bt = beta[col0 + col];
    const float ab = att_bias[col0 + col], dw = dec_w[col0 + col];
#pragma unroll 4
    for (int r = 0; r < 16; r++) {
        int row = seg * 16 + r;
        float h  = sH[row * SHS + col];
        float hn = (h - mean) * rstd * gm + bt;
        float th = tanhf(hn);
        float z  = sT[row * SHS + col] + ab;
        float sg = 1.0f / (1.0f + __expf(-z));
        float o  = th * sg;
        long ofs = (long)row * P_ + col0 + col;
        out_outcome[ofs] = o;
        out_att[ofs]     = sg;
        float p = o * dw;
#pragma unroll
        for (int off = 16; off > 0; off >>= 1)
            p += __shfl_xor_sync(0xffffffffu, p, off);
        if (col == 0) g_dpart[row * NCTA + blockIdx.x] = p;
    }
}

__global__ __launch_bounds__(512) void bioxnet_decision_kernel(
    const float* __restrict__ dec_b, float* __restrict__ out_dec)
{
    __shared__ float red[4][B_];
    int t = threadIdx.x;
    int row = t >> 2;
    int seg = t & 3;
    const float4* p = (const float4*)(g_dpart + row * NCTA + seg * 32);
    float s = 0.f;
#pragma unroll
    for (int i = 0; i < 8; i++) {
        float4 v = p[i];
        s += v.x + v.y + v.z + v.w;
    }
    red[seg][row] = s;
    __syncthreads();
    if (t < B_) out_dec[t] = dec_b[0] + red[0][t] + red[1][t] + red[2][t] + red[3][t];
}

extern "C" void kernel_launch(void* const* d_in, const int* in_sizes, int n_in,
                              void* d_out, int out_size)
{
    (void)in_sizes; (void)n_in; (void)out_size;
    const float* A        = (const float*)d_in[0];
    const float* mapp     = (const float*)d_in[1];
    const float* Wk       = (const float*)d_in[2];
    // d_in[3] = bias: cancels exactly in batchnorm mean subtraction
    const float* Wa       = (const float*)d_in[4];
    const float* att_bias = (const float*)d_in[5];
    const float* gamma    = (const float*)d_in[6];
    const float* beta     = (const float*)d_in[7];
    const float* dec_w    = (const float*)d_in[8];
    const float* dec_b    = (const float*)d_in[9];

    float* out = (float*)d_out;
    float* out_outcome = out;
    float* out_dec     = out + (long)B_ * P_;
    float* out_att     = out + (long)B_ * P_ + B_;

    cudaFuncSetAttribute(bioxnet_fused_kernel,
                         cudaFuncAttributeMaxDynamicSharedMemorySize, SMEM_DYN);

    presplit_kernel<<<2500, 256>>>(A);
    bioxnet_fused_kernel<<<NCTA, 256, SMEM_DYN>>>(mapp, Wk, Wa, att_bias,
                                                  gamma, beta, dec_w,
                                                  out_outcome, out_att);
    bioxnet_decision_kernel<<<1, 512>>>(dec_b, out_dec);
}

// round 14
// speedup vs baseline: 1.5225x; 1.1303x over previous
#include <cuda_runtime.h>
#include <cuda_fp16.h>
#include <stdint.h>

#define B_  128
#define G_  20000
#define P_  4096
#define KT  32
#define NT  32
#define NCB    (P_/NT)     // 128 column blocks
#define NCHUNK (G_/KT)     // 625 exact
#define KS0    313         // chunks for ks=0; ks=1 gets 312
#define BN_EPS 1e-5f

// dynamic smem byte offsets (per CTA <= 113 KB for occupancy 2)
#define A_ROWB     80                  // 32 halves + 16B pad -> u32 stride 20, conflict-free
#define A_STAGE_B  (128*A_ROWB)        // 10240; ring of 4
#define WF32_BASE  (4*A_STAGE_B)       // 40960
#define WF32_STAGE 12288               // Wk 4KB | mapp 4KB | Wa 4KB; ring of 4
#define WF16_BASE  (WF32_BASE + 4*WF32_STAGE)   // 90112
#define W_ARR_B    2560                // fp16 [n][k] stride-20 array
#define WF16_STAGE (2*W_ARR_B)         // W + T; ring of 2
#define SMEM_DYN   (WF16_BASE + 2*WF16_STAGE + 128)   // 100480 (~98 KB)

__device__ __half g_Ah[B_ * G_];
// per column-block: [ks0_H 4096 | ks0_T 4096 | ks1_H 4096 | ks1_T 4096] floats
__device__ float g_part[NCB * 16384];
__device__ float g_dpart[B_ * NCB];

__device__ __forceinline__ uint32_t smem_u32(const void* p) {
    uint32_t a;
    asm("{ .reg .u64 t; cvta.to.shared.u64 t, %1; cvt.u32.u64 %0, t; }"
        : "=r"(a) : "l"(p));
    return a;
}
#define CPA16(dst, src) \
    asm volatile("cp.async.cg.shared.global [%0], [%1], 16;" :: "r"(dst), "l"(src))
#define CPA_COMMIT() asm volatile("cp.async.commit_group;")
#define CPA_WAIT2()  asm volatile("cp.async.wait_group 2;")

__device__ __forceinline__ void mma_f16(float* d, const uint32_t* a, uint32_t b0, uint32_t b1) {
    asm volatile(
        "mma.sync.aligned.m16n8k16.row.col.f32.f16.f16.f32 "
        "{%0,%1,%2,%3}, {%4,%5,%6,%7}, {%8,%9}, {%0,%1,%2,%3};"
        : "+f"(d[0]), "+f"(d[1]), "+f"(d[2]), "+f"(d[3])
        : "r"(a[0]), "r"(a[1]), "r"(a[2]), "r"(a[3]), "r"(b0), "r"(b1));
}

// ---------------- pre-convert A: fp32 -> fp16 global ----------------
__global__ __launch_bounds__(256) void presplit_kernel(const float* __restrict__ A) {
    int i4 = blockIdx.x * 256 + threadIdx.x;   // 640000 float4s exactly
    float4 v = ((const float4*)A)[i4];
    __half2 h0 = __floats2half2_rn(v.x, v.y);
    __half2 h1 = __floats2half2_rn(v.z, v.w);
    ((uint2*)g_Ah)[i4] = make_uint2(*(uint32_t*)&h0, *(uint32_t*)&h1);
}

// ---------------- mainloop kernel: K-split GEMM partials ----------------
__global__ __launch_bounds__(256, 2) void bioxnet_main_kernel(
    const float* __restrict__ mapp, const float* __restrict__ Wk,
    const float* __restrict__ Wa)
{
    extern __shared__ __align__(16) char sp[];

    const int tid  = threadIdx.x;
    const int lane = tid & 31;
    const int wrp  = tid >> 5;
    const int gr   = lane >> 2;   // 0..7
    const int tc   = lane & 3;    // 0..3
    const int wr   = wrp >> 1;    // 0..3: 32-row group
    const int wc   = wrp & 1;     // 0..1: 16-col group
    const int ks   = blockIdx.x >> 7;      // K-split half
    const int cb   = blockIdx.x & 127;     // column block
    const int col0 = cb * NT;
    const int base = ks * KS0;
    const int NC   = KS0 - ks;             // 313 or 312 chunks
    const uint32_t sb = smem_u32(sp);

    // A cp.async: thread -> (row = tid>>1, 2 of 4 16B units)
    const int arow = tid >> 1;
    const int auh  = (tid & 1) * 2;
    const __half* gH = g_Ah + (long)arow * G_ + auh * 8;
    const uint32_t ad0 = (uint32_t)(arow * A_ROWB + auh * 16);

#define CPA_A(chunk, st) do {                                 \
        uint32_t _b = sb + (uint32_t)(st) * A_STAGE_B + ad0;  \
        const __half* _h = gH + (chunk) * KT;                 \
        CPA16(_b, _h);  CPA16(_b + 16, _h + 8);               \
    } while (0)

    // W cp.async: thread -> row wkr0 = tid>>3, 16B unit wc0 = tid&7, one per array
    const int wkr0 = tid >> 3;
    const int wc0  = tid & 7;
    const long wgo = (long)wkr0 * P_ + col0 + wc0 * 4;
    const uint32_t wd0 = (uint32_t)(wkr0 * 128 + wc0 * 16);

#define CPA_W(chunk, st) do {                                             \
        uint32_t _b = sb + WF32_BASE + (uint32_t)(st) * WF32_STAGE + wd0; \
        long _g = (long)(chunk) * KT * P_ + wgo;                          \
        CPA16(_b,         Wk   + _g);                                     \
        CPA16(_b + 4096,  mapp + _g);                                     \
        CPA16(_b + 8192,  Wa   + _g);                                     \
    } while (0)

    // CONV: thread -> col wn, 4 k rows starting wkq*4 (reads staged fp32)
    const int wn  = tid & 31;
    const int wkq = tid >> 5;   // 0..7

#define CONV_W(st32, st16) do {                                                   \
        const float* _f = (const float*)(sp + WF32_BASE + (st32) * WF32_STAGE);   \
        uint32_t* _w = (uint32_t*)(sp + WF16_BASE + (st16) * WF16_STAGE);         \
        uint32_t* _t = _w + (W_ARR_B / 4);                                        \
        const int _k0 = wkq * 4;                                                  \
        float _a0 = _f[(_k0    ) * 32 + wn], _m0 = _f[1024 + (_k0    ) * 32 + wn];\
        float _a1 = _f[(_k0 + 1) * 32 + wn], _m1 = _f[1024 + (_k0 + 1) * 32 + wn];\
        float _a2 = _f[(_k0 + 2) * 32 + wn], _m2 = _f[1024 + (_k0 + 2) * 32 + wn];\
        float _a3 = _f[(_k0 + 3) * 32 + wn], _m3 = _f[1024 + (_k0 + 3) * 32 + wn];\
        int _o = wn * 20 + wkq * 2;                                               \
        __half2 _p0 = __floats2half2_rn(_a0 * _m0, _a1 * _m1);                    \
        __half2 _p1 = __floats2half2_rn(_a2 * _m2, _a3 * _m3);                    \
        _w[_o] = *(uint32_t*)&_p0; _w[_o + 1] = *(uint32_t*)&_p1;                 \
        _a0 = _f[2048 + (_k0    ) * 32 + wn];                                     \
        _a1 = _f[2048 + (_k0 + 1) * 32 + wn];                                     \
        _a2 = _f[2048 + (_k0 + 2) * 32 + wn];                                     \
        _a3 = _f[2048 + (_k0 + 3) * 32 + wn];                                     \
        _p0 = __floats2half2_rn(_a0, _a1);                                        \
        _p1 = __floats2half2_rn(_a2, _a3);                                        \
        _t[_o] = *(uint32_t*)&_p0; _t[_o + 1] = *(uint32_t*)&_p1;                 \
    } while (0)

    float accH[2][2][4], accT[2][2][4];
#pragma unroll
    for (int rt = 0; rt < 2; rt++)
#pragma unroll
        for (int nt = 0; nt < 2; nt++)
#pragma unroll
            for (int i = 0; i < 4; i++) { accH[rt][nt][i] = 0.f; accT[rt][nt][i] = 0.f; }

    // MMA body for local chunk j: A stage j&3, fp16 stage j&1
#define MMA_CHUNK(j) do {                                                          \
        const uint32_t* aH = (const uint32_t*)(sp + ((j) & 3) * A_STAGE_B);        \
        const uint32_t* wW = (const uint32_t*)(sp + WF16_BASE + ((j) & 1) * WF16_STAGE); \
        const uint32_t* wT = wW + (W_ARR_B / 4);                                   \
        _Pragma("unroll")                                                          \
        for (int kh = 0; kh < 2; kh++) {                                           \
            uint32_t ah[2][4];                                                     \
            _Pragma("unroll")                                                      \
            for (int rt = 0; rt < 2; rt++) {                                       \
                const int o = (wr * 32 + rt * 16 + gr) * 20 + kh * 8 + tc;         \
                ah[rt][0] = aH[o];                                                 \
                ah[rt][1] = aH[o + 160];                                           \
                ah[rt][2] = aH[o + 4];                                             \
                ah[rt][3] = aH[o + 164];                                           \
            }                                                                      \
            _Pragma("unroll")                                                      \
            for (int nt = 0; nt < 2; nt++) {                                       \
                const int o = (wc * 16 + nt * 8 + gr) * 20 + kh * 8 + tc;          \
                uint32_t w0 = wW[o], w1 = wW[o + 4];                               \
                uint32_t t0 = wT[o], t1 = wT[o + 4];                               \
                _Pragma("unroll")                                                  \
                for (int rt = 0; rt < 2; rt++) {                                   \
                    mma_f16(accH[rt][nt], ah[rt], w0, w1);                         \
                    mma_f16(accT[rt][nt], ah[rt], t0, t1);                         \
                }                                                                  \
            }                                                                      \
        }                                                                          \
    } while (0)

    // -------- prologue: local chunks 0,1 in flight --------
    CPA_A(base + 0, 0); CPA_W(base + 0, 0); CPA_COMMIT();
    CPA_A(base + 1, 1); CPA_W(base + 1, 1); CPA_COMMIT();

#pragma unroll 1
    for (int i = 0; i < NC; i++) {
        __syncthreads();   // CONV(i-1) + MMA(i-2) complete CTA-wide

        // prefetch local chunk i+2: A stage (i+2)&3 (vs MMA read (i-1)&3: disjoint),
        // W32 stage (i+2)&3 (vs CONV read i&3: disjoint)
        if (i + 2 < NC) { CPA_A(base + i + 2, (i + 2) & 3); CPA_W(base + i + 2, (i + 2) & 3); }
        CPA_COMMIT();      // unconditional: uniform group count

        if (i > 0) MMA_CHUNK(i - 1);   // overlaps in-flight cp.async

        CPA_WAIT2();       // pending <= {i+1, i+2} -> chunk i landed
        CONV_W(i & 3, i & 1);
    }
    __syncthreads();
    MMA_CHUNK(NC - 1);

    // ---- write partial accumulators to global scratch ----
    float* pH = g_part + (long)cb * 16384 + ks * 8192;
    float* pT = pH + 4096;
#pragma unroll
    for (int rt = 0; rt < 2; rt++) {
#pragma unroll
        for (int nt = 0; nt < 2; nt++) {
            const int row0 = wr * 32 + rt * 16 + gr;
            const int col  = wc * 16 + nt * 8 + 2 * tc;
            *(float2*)&pH[(row0    ) * 32 + col] = make_float2(accH[rt][nt][0], accH[rt][nt][1]);
            *(float2*)&pH[(row0 + 8) * 32 + col] = make_float2(accH[rt][nt][2], accH[rt][nt][3]);
            *(float2*)&pT[(row0    ) * 32 + col] = make_float2(accT[rt][nt][0], accT[rt][nt][1]);
            *(float2*)&pT[(row0 + 8) * 32 + col] = make_float2(accT[rt][nt][2], accT[rt][nt][3]);
        }
    }
}

// ---------------- epilogue: combine partials, BN, activations ----------------
__global__ __launch_bounds__(256) void bioxnet_post_kernel(
    const float* __restrict__ att_bias, const float* __restrict__ gamma,
    const float* __restrict__ beta, const float* __restrict__ dec_w,
    float* __restrict__ out_outcome, float* __restrict__ out_att)
{
    __shared__ float redS[8][NT], redQ[8][NT], s_mean[NT], s_rstd[NT];
    const int cb  = blockIdx.x;
    const int tid = threadIdx.x;
    const int col = tid & 31;
    const int seg = tid >> 5;
    const int col0 = cb * NT;
    const float* p = g_part + (long)cb * 16384;

    float h[16], t[16];
    float s = 0.f, q = 0.f;
#pragma unroll
    for (int r = 0; r < 16; r++) {
        int row = seg * 16 + r;
        h[r] = p[row * 32 + col] + p[8192 + row * 32 + col];
        t[r] = p[4096 + row * 32 + col] + p[12288 + row * 32 + col];
        s += h[r]; q += h[r] * h[r];
    }
    redS[seg][col] = s;
    redQ[seg][col] = q;
    __syncthreads();
    if (tid < 32) {
        float ss = 0.f, qq = 0.f;
#pragma unroll
        for (int i = 0; i < 8; i++) { ss += redS[i][tid]; qq += redQ[i][tid]; }
        float mean = ss * (1.0f / B_);
        float var  = qq * (1.0f / B_) - mean * mean;
        s_mean[tid] = mean;
        s_rstd[tid] = rsqrtf(var + BN_EPS);
    }
    __syncthreads();

    const float mean = s_mean[col], rstd = s_rstd[col];
    const float gm = gamma[col0 + col], bt = beta[col0 + col];
    const float ab = att_bias[col0 + col], dw = dec_w[col0 + col];
#pragma unroll
    for (int r = 0; r < 16; r++) {
        int row = seg * 16 + r;
        float hn = (h[r] - mean) * rstd * gm + bt;
        float th = tanhf(hn);
        float sg = 1.0f / (1.0f + __expf(-(t[r] + ab)));
        float o  = th * sg;
        long ofs = (long)row * P_ + col0 + col;
        out_outcome[ofs] = o;
        out_att[ofs]     = sg;
        float pp = o * dw;
#pragma unroll
        for (int off = 16; off > 0; off >>= 1)
            pp += __shfl_xor_sync(0xffffffffu, pp, off);
        if (col == 0) g_dpart[row * NCB + cb] = pp;
    }
}

__global__ __launch_bounds__(512) void bioxnet_decision_kernel(
    const float* __restrict__ dec_b, float* __restrict__ out_dec)
{
    __shared__ float red[4][B_];
    int t = threadIdx.x;
    int row = t >> 2;
    int seg = t & 3;
    const float4* p = (const float4*)(g_dpart + row * NCB + seg * 32);
    float s = 0.f;
#pragma unroll
    for (int i = 0; i < 8; i++) {
        float4 v = p[i];
        s += v.x + v.y + v.z + v.w;
    }
    red[seg][row] = s;
    __syncthreads();
    if (t < B_) out_dec[t] = dec_b[0] + red[0][t] + red[1][t] + red[2][t] + red[3][t];
}

extern "C" void kernel_launch(void* const* d_in, const int* in_sizes, int n_in,
                              void* d_out, int out_size)
{
    (void)in_sizes; (void)n_in; (void)out_size;
    const float* A        = (const float*)d_in[0];
    const float* mapp     = (const float*)d_in[1];
    const float* Wk       = (const float*)d_in[2];
    // d_in[3] = bias: cancels exactly in batchnorm mean subtraction
    const float* Wa       = (const float*)d_in[4];
    const float* att_bias = (const float*)d_in[5];
    const float* gamma    = (const float*)d_in[6];
    const float* beta     = (const float*)d_in[7];
    const float* dec_w    = (const float*)d_in[8];
    const float* dec_b    = (const float*)d_in[9];

    float* out = (float*)d_out;
    float* out_outcome = out;
    float* out_dec     = out + (long)B_ * P_;
    float* out_att     = out + (long)B_ * P_ + B_;

    cudaFuncSetAttribute(bioxnet_main_kernel,
                         cudaFuncAttributeMaxDynamicSharedMemorySize, SMEM_DYN);

    presplit_kernel<<<2500, 256>>>(A);
    bioxnet_main_kernel<<<2 * NCB, 256, SMEM_DYN>>>(mapp, Wk, Wa);
    bioxnet_post_kernel<<<NCB, 256>>>(att_bias, gamma, beta, dec_w,
                                      out_outcome, out_att);
    bioxnet_decision_kernel<<<1, 512>>>(dec_b, out_dec);
}